// round 14
// baseline (speedup 1.0000x reference)
#include <cuda_runtime.h>
#include <math.h>

// x (B=32, C=256, H=64, W=64) fp32; s=mean_c(x); h=relu(s*w1+b1)[16];
// scale=sigmoid(w2@h+b2); out=x*scale
// Identity: z[c] = w2[c]@relu(s*w1+b1)+b2[c] is piecewise-linear in s:
//   z[c] = A[c,i]*s + B[c,i],  i = #{k : s > t_k},  t_k = -b1[k]/w1[k]
// R14: R13 + (a) intra-warp shfl pre-reduce in pass 1 (warp's 2 channel
// groups share the same 16 pixels -> one shfl_xor(16) folds them; red4
// halves to 16 partials), (b) sigmoid halves folded into the AB table
// (store A/2,B/2; o = fma(v/2, tanh(z/2), v/2)) saving 1 FMUL/element.

#define B_    32
#define CH    256
#define HW4   1024          // 4096/4 float4 per (b,c) row
#define HID   16
#define P4    16            // float4 pixels per tile (64 px)
#define TPB   512
#define NGRP  32            // channel groups (t>>4)
#define NPAIR 16            // warp-folded group pairs
#define CPT   8             // channels per thread -> v[8] = 32 regs
#define NTILE 2048          // 32 images * 64 tiles/image
#define GRID  296           // 2 persistent CTAs per SM * 148

__device__ __forceinline__ float tanh_approx(float z) {
    float th;
    asm("tanh.approx.f32 %0, %1;" : "=f"(th) : "f"(z));
    return th;
}

__global__ __launch_bounds__(TPB, 2)
void pse_fused_kernel(const float4* __restrict__ x,
                      const float*  __restrict__ w1,
                      const float*  __restrict__ b1,
                      const float*  __restrict__ w2,
                      const float*  __restrict__ b2,
                      float4* __restrict__ out)
{
    __shared__ float2 AB[CH * 17];        // 34,816 B table: (A/2, B/2)
    __shared__ float4 red4[NPAIR * P4];   //  4,096 B pair partial sums
    __shared__ float4 s4b[P4];
    __shared__ int4   i4b[P4];
    __shared__ float  us[HID];
    __shared__ float  reps[HID + 1];

    const int t = threadIdx.x;
    const int q = t & (P4 - 1);           // float4-pixel 0..15
    const int g = t >> 4;                 // channel group 0..31
    const float INF = __int_as_float(0x7f800000);

    // ---------- per-CTA prologue: build piecewise-linear table ----------
    if (t < HID) {
        float w = w1[t], b = b1[t];
        float myth = (w != 0.0f) ? (-b / w) : INF;
        int rank = 0;
        #pragma unroll
        for (int k = 0; k < HID; k++) {
            float wk = w1[k], bk = b1[k];
            float tk = (wk != 0.0f) ? (-bk / wk) : INF;
            rank += (tk < myth) || (tk == myth && k < t);
        }
        us[rank] = myth;
    }
    __syncthreads();
    if (t < HID + 1) {
        float lo = (t == 0)   ? -INF : us[t - 1];
        float hi = (t == HID) ?  INF : us[t];
        bool flo = isfinite(lo), fhi = isfinite(hi);
        if (!flo && !fhi)      { lo = -1.0f; hi = 1.0f; }
        else if (!flo)         lo = hi - 2.0f;
        else if (!fhi)         hi = lo + 2.0f;
        reps[t] = 0.5f * (lo + hi);
    }
    __syncthreads();
    {   // 512 threads, 2 per channel: thread handles intervals i%2 == t&1
        const int c = t >> 1;
        const int half = t & 1;
        float w2r[HID];
        #pragma unroll
        for (int k = 0; k < HID; k++) w2r[k] = w2[c * HID + k];
        const float bc = b2[c];
        for (int i = half; i < 17; i += 2) {
            const float rep = reps[i];
            float a = 0.0f, bb = bc;
            #pragma unroll
            for (int k = 0; k < HID; k++) {
                float wk = w1[k], bk = b1[k];
                if (fmaf(rep, wk, bk) > 0.0f) {   // unit k active on interval i
                    a  = fmaf(w2r[k], wk, a);
                    bb = fmaf(w2r[k], bk, bb);
                }
            }
            AB[c * 17 + i] = make_float2(0.5f * a, 0.5f * bb);  // halves folded
        }
    }
    __syncthreads();

    // ---------- persistent tile loop (R5/R13 geometry) ----------
    for (int tile = blockIdx.x; tile < NTILE; tile += GRID) {
        const int img   = tile >> 6;          // 64 tiles per image
        const int base4 = (tile & 63) << 4;
        const float4* xb = x   + (size_t)img * CH * HW4 + base4;
        float4*       ob = out + (size_t)img * CH * HW4 + base4;

        // pass 1: 8 independent LDG.128 into registers (kept live), + sums
        float4 v[CPT];
        #pragma unroll
        for (int j = 0; j < CPT; j++)
            v[j] = __ldcs(&xb[(g + j * NGRP) * HW4 + q]);   // read-once data

        float4 s = make_float4(0.f, 0.f, 0.f, 0.f);
        #pragma unroll
        for (int j = 0; j < CPT; j++) {
            s.x += v[j].x; s.y += v[j].y; s.z += v[j].z; s.w += v[j].w;
        }
        // fold the warp's two channel groups (lanes 0-15 vs 16-31 share the
        // same pixel set) with one butterfly step; lanes<16 publish.
        s.x += __shfl_xor_sync(0xffffffffu, s.x, 16);
        s.y += __shfl_xor_sync(0xffffffffu, s.y, 16);
        s.z += __shfl_xor_sync(0xffffffffu, s.z, 16);
        s.w += __shfl_xor_sync(0xffffffffu, s.w, 16);
        if ((t & 31) < 16)
            red4[(t >> 5) * P4 + q] = s;      // pair (t>>5), pixel q
        __syncthreads();

        // warp-0 two-half reduce over 16 pair-partials: lane l -> pixel
        // w=l&15, half h=l>>4 sums 8 pairs; shfl_xor(16) merges; classify.
        if (t < 32) {
            const int w = t & 15, h = t >> 4;
            float4 acc = red4[(h * 8) * P4 + w];
            #pragma unroll
            for (int p2 = 1; p2 < 8; p2++) {
                float4 r = red4[(h * 8 + p2) * P4 + w];
                acc.x += r.x; acc.y += r.y; acc.z += r.z; acc.w += r.w;
            }
            acc.x += __shfl_xor_sync(0xffffffffu, acc.x, 16);
            acc.y += __shfl_xor_sync(0xffffffffu, acc.y, 16);
            acc.z += __shfl_xor_sync(0xffffffffu, acc.z, 16);
            acc.w += __shfl_xor_sync(0xffffffffu, acc.w, 16);
            if (h == 0) {
                const float inv = 1.0f / (float)CH;
                float4 sv = make_float4(acc.x*inv, acc.y*inv, acc.z*inv, acc.w*inv);
                int4 iv = make_int4(0, 0, 0, 0);
                #pragma unroll
                for (int k = 0; k < HID; k++) {
                    const float tk = us[k];
                    iv.x += (sv.x > tk); iv.y += (sv.y > tk);
                    iv.z += (sv.z > tk); iv.w += (sv.w > tk);
                }
                s4b[w] = sv; i4b[w] = iv;
            }
        }
        __syncthreads();

        // pass 2: z/2 = A'*s+B'; o = fma(v/2, tanh(z/2), v/2)
        const float4 sv = s4b[q];
        const int4   iv = i4b[q];
        #pragma unroll
        for (int j = 0; j < CPT; j++) {
            const int c = g + j * NGRP;
            const float2* row = AB + c * 17;
            const float2 a0 = row[iv.x], a1 = row[iv.y],
                         a2 = row[iv.z], a3 = row[iv.w];
            const float t0 = tanh_approx(fmaf(a0.x, sv.x, a0.y));
            const float t1 = tanh_approx(fmaf(a1.x, sv.y, a1.y));
            const float t2 = tanh_approx(fmaf(a2.x, sv.z, a2.y));
            const float t3 = tanh_approx(fmaf(a3.x, sv.w, a3.y));
            const float h0 = 0.5f * v[j].x;
            const float h1 = 0.5f * v[j].y;
            const float h2 = 0.5f * v[j].z;
            const float h3 = 0.5f * v[j].w;
            float4 o;
            o.x = fmaf(h0, t0, h0);
            o.y = fmaf(h1, t1, h1);
            o.z = fmaf(h2, t2, h2);
            o.w = fmaf(h3, t3, h3);
            __stcs(&ob[c * HW4 + q], o);                    // never re-read
        }
        // next tile's red4/s4b writes are fenced by its own __syncthreads()
    }
}

extern "C" void kernel_launch(void* const* d_in, const int* in_sizes, int n_in,
                              void* d_out, int out_size)
{
    pse_fused_kernel<<<GRID, TPB>>>((const float4*)d_in[0],
                                    (const float*)d_in[1],
                                    (const float*)d_in[2],
                                    (const float*)d_in[3],
                                    (const float*)d_in[4],
                                    (float4*)d_out);
}